// round 1
// baseline (speedup 1.0000x reference)
#include <cuda_runtime.h>
#include <math.h>

#define NNODES 100000
#define NEDGES 1600000

// ---------------- scratch (static device globals; no allocations) ----------------
__device__ float g_big1[(size_t)NNODES * 192];   // x3 then gi
__device__ float g_big2[(size_t)NNODES * 192];   // gh
__device__ float g_out [(size_t)NNODES * 64];    // h0 / embed lin
__device__ float g_h   [(size_t)NNODES * 64];    // GRU hidden
__device__ float g_swh [(size_t)NNODES * 64];    // aggregated messages
__device__ float g_tmp [(size_t)NNODES * 64];    // head hidden
__device__ float g_stats[128];                   // sum[64], sumsq[64]
__device__ float g_scale[4 * 64];
__device__ float g_shift[4 * 64];
__device__ int   g_rowptr[NNODES + 1];
__device__ int   g_cursor[NNODES];
__device__ int   g_eidx[NEDGES];
__device__ int   g_bsums[128];

// ---------------- CSR build ----------------
__global__ void k_count(const int* __restrict__ dst, int* __restrict__ cnt) {
    int e = blockIdx.x * blockDim.x + threadIdx.x;
    if (e < NEDGES) atomicAdd(&cnt[dst[e]], 1);
}

__global__ void k_scanA(const int* __restrict__ cnt, int* __restrict__ bsums) {
    __shared__ int sh[1024];
    int i = blockIdx.x * 1024 + threadIdx.x;
    sh[threadIdx.x] = (i < NNODES) ? cnt[i] : 0;
    __syncthreads();
    for (int off = 512; off > 0; off >>= 1) {
        if (threadIdx.x < off) sh[threadIdx.x] += sh[threadIdx.x + off];
        __syncthreads();
    }
    if (threadIdx.x == 0) bsums[blockIdx.x] = sh[0];
}

__global__ void k_scanB(int* __restrict__ bsums, int nb, int* __restrict__ rowptr) {
    __shared__ int sh[128];
    int t = threadIdx.x;
    int orig = (t < nb) ? bsums[t] : 0;
    sh[t] = orig;
    __syncthreads();
    for (int off = 1; off < 128; off <<= 1) {
        int v = (t >= off) ? sh[t - off] : 0;
        __syncthreads();
        sh[t] += v;
        __syncthreads();
    }
    if (t < nb) bsums[t] = sh[t] - orig;   // exclusive
    if (t == 0) rowptr[NNODES] = NEDGES;
}

__global__ void k_scanC(int* __restrict__ cnt, const int* __restrict__ bsums,
                        int* __restrict__ rowptr, int* __restrict__ cursor) {
    __shared__ int sh[1024];
    int i = blockIdx.x * 1024 + threadIdx.x;
    int orig = (i < NNODES) ? cnt[i] : 0;
    sh[threadIdx.x] = orig;
    __syncthreads();
    for (int off = 1; off < 1024; off <<= 1) {
        int v = (threadIdx.x >= off) ? sh[threadIdx.x - off] : 0;
        __syncthreads();
        sh[threadIdx.x] += v;
        __syncthreads();
    }
    if (i < NNODES) {
        int start = bsums[blockIdx.x] + sh[threadIdx.x] - orig;
        rowptr[i] = start;
        cursor[i] = start;
    }
}

__global__ void k_scatter(const int* __restrict__ dst, int* __restrict__ cursor,
                          int* __restrict__ eidx) {
    int e = blockIdx.x * blockDim.x + threadIdx.x;
    if (e < NEDGES) {
        int pos = atomicAdd(&cursor[dst[e]], 1);
        eidx[pos] = e;
    }
}

// ---------------- generic 64-in matmul, 64-out per y-group ----------------
// C[n, blockIdx.y*64 + k] = act(A[n,:]) dot W_col(k)  (+ bias)
// W layout: transW ? W[k*64+d] : W[d*64+k] (after adding blockIdx.y*w_blk_stride)
// in_act: 0 none, 1 affine (x*scale[d]+shift[d])
// stats (optional, grid.y==1 only): accumulate per-column sum & sumsq of outputs
__global__ __launch_bounds__(256) void k_mm64(
    const float* __restrict__ A,
    const float* __restrict__ W, int transW, int w_blk_stride,
    const float* __restrict__ bias, int bias_blk,
    const float* __restrict__ in_scale, const float* __restrict__ in_shift, int in_act,
    float* __restrict__ C, int c_stride,
    float* __restrict__ stats)
{
    __shared__ float Ws[64 * 64];
    __shared__ float As[96 * 64];
    __shared__ float ssum[64], ssq[64];
    int tid = threadIdx.y * 16 + threadIdx.x;
    const float* Wb = W + (size_t)blockIdx.y * w_blk_stride;
    for (int i = tid; i < 4096; i += 256) {
        int d = i >> 6, k = i & 63;
        Ws[i] = transW ? Wb[k * 64 + d] : Wb[i];
    }
    int nbase = blockIdx.x * 96;
    for (int i = tid; i < 96 * 64; i += 256) {
        int n = nbase + (i >> 6);
        float v = (n < NNODES) ? A[(size_t)n * 64 + (i & 63)] : 0.f;
        if (in_act) { int c = i & 63; v = v * in_scale[c] + in_shift[c]; }
        As[i] = v;
    }
    if (stats && tid < 64) { ssum[tid] = 0.f; ssq[tid] = 0.f; }
    __syncthreads();

    int kx = threadIdx.x;
    float4 acc[6];
#pragma unroll
    for (int j = 0; j < 6; j++) acc[j] = make_float4(0.f, 0.f, 0.f, 0.f);
#pragma unroll 8
    for (int d = 0; d < 64; d++) {
        float4 w = reinterpret_cast<const float4*>(Ws + d * 64)[kx];
#pragma unroll
        for (int j = 0; j < 6; j++) {
            float a = As[(threadIdx.y + 16 * j) * 64 + d];
            acc[j].x = fmaf(a, w.x, acc[j].x);
            acc[j].y = fmaf(a, w.y, acc[j].y);
            acc[j].z = fmaf(a, w.z, acc[j].z);
            acc[j].w = fmaf(a, w.w, acc[j].w);
        }
    }
    float4 b4 = make_float4(0.f, 0.f, 0.f, 0.f);
    if (bias) {
        const float* bb = bias + blockIdx.y * bias_blk;
        b4.x = bb[kx * 4 + 0]; b4.y = bb[kx * 4 + 1];
        b4.z = bb[kx * 4 + 2]; b4.w = bb[kx * 4 + 3];
    }
    float s0 = 0, s1 = 0, s2 = 0, s3 = 0, q0 = 0, q1 = 0, q2 = 0, q3 = 0;
#pragma unroll
    for (int j = 0; j < 6; j++) {
        int node = nbase + threadIdx.y + 16 * j;
        if (node < NNODES) {
            float v0 = acc[j].x + b4.x, v1 = acc[j].y + b4.y;
            float v2 = acc[j].z + b4.z, v3 = acc[j].w + b4.w;
            float* cp = C + (size_t)node * c_stride + blockIdx.y * 64 + kx * 4;
            *reinterpret_cast<float4*>(cp) = make_float4(v0, v1, v2, v3);
            s0 += v0; s1 += v1; s2 += v2; s3 += v3;
            q0 += v0 * v0; q1 += v1 * v1; q2 += v2 * v2; q3 += v3 * v3;
        }
    }
    if (stats) {
        atomicAdd(&ssum[kx * 4 + 0], s0); atomicAdd(&ssum[kx * 4 + 1], s1);
        atomicAdd(&ssum[kx * 4 + 2], s2); atomicAdd(&ssum[kx * 4 + 3], s3);
        atomicAdd(&ssq [kx * 4 + 0], q0); atomicAdd(&ssq [kx * 4 + 1], q1);
        atomicAdd(&ssq [kx * 4 + 2], q2); atomicAdd(&ssq [kx * 4 + 3], q3);
        __syncthreads();
        if (tid < 64) {
            atomicAdd(&stats[tid], ssum[tid]);
            atomicAdd(&stats[64 + tid], ssq[tid]);
        }
    }
}

// ---------------- BN helpers ----------------
__global__ void k_finalize(const float* __restrict__ stats, const float* __restrict__ gamma,
                           const float* __restrict__ beta, float* __restrict__ scale,
                           float* __restrict__ shift) {
    int k = threadIdx.x;
    const float invN = 1.0f / (float)NNODES;
    float mean = stats[k] * invN;
    float var = stats[64 + k] * invN - mean * mean;
    float sc = gamma[k] * rsqrtf(var + 1e-5f);
    scale[k] = sc;
    shift[k] = beta[k] - mean * sc;
}

__global__ void k_bnrelu(float* __restrict__ X, const float* __restrict__ scale,
                         const float* __restrict__ shift) {
    size_t idx = (size_t)blockIdx.x * blockDim.x + threadIdx.x;
    if (idx < (size_t)NNODES * 64) {
        int k = (int)(idx & 63);
        float v = X[idx] * scale[k] + shift[k];
        X[idx] = fmaxf(v, 0.f);
    }
}

__global__ void k_stats64(const float* __restrict__ X, float* __restrict__ stats) {
    __shared__ float ssum[64], ssq[64];
    int k = threadIdx.x, ty = threadIdx.y;
    if (ty == 0) { ssum[k] = 0.f; ssq[k] = 0.f; }
    __syncthreads();
    float s = 0.f, q = 0.f;
    for (int n = blockIdx.x * 4 + ty; n < NNODES; n += gridDim.x * 4) {
        float v = X[(size_t)n * 64 + k];
        s += v; q += v * v;
    }
    atomicAdd(&ssum[k], s); atomicAdd(&ssq[k], q);
    __syncthreads();
    if (ty == 0) { atomicAdd(&stats[k], ssum[k]); atomicAdd(&stats[64 + k], ssq[k]); }
}

// ---------------- edge aggregation (gather, warp per node) ----------------
__global__ void k_aggregate(const float* __restrict__ x3, const int* __restrict__ rowptr,
                            const int* __restrict__ eidx, const int* __restrict__ src,
                            const int* __restrict__ rel, const float* __restrict__ norm,
                            float* __restrict__ swh) {
    int warp = (blockIdx.x * blockDim.x + threadIdx.x) >> 5;
    int lane = threadIdx.x & 31;
    if (warp >= NNODES) return;
    int beg = rowptr[warp], end = rowptr[warp + 1];
    float a0 = 0.f, a1 = 0.f;
    for (int e = beg; e < end; ++e) {
        int id = eidx[e];
        int s = src[id];
        int r = rel[id];
        float w = norm[id];
        const float* row = x3 + (size_t)s * 192 + r * 64;
        a0 = fmaf(row[lane], w, a0);
        a1 = fmaf(row[lane + 32], w, a1);
    }
    size_t o = (size_t)warp * 64;
    swh[o + lane] = a0;
    swh[o + lane + 32] = a1;
}

// ---------------- GRU gate fusion ----------------
__device__ __forceinline__ float sigm(float x) { return 1.0f / (1.0f + expf(-x)); }

__global__ void k_gates(const float* __restrict__ gi, const float* __restrict__ gh,
                        float* __restrict__ h) {
    size_t idx = (size_t)blockIdx.x * blockDim.x + threadIdx.x;
    if (idx >= (size_t)NNODES * 64) return;
    int n = (int)(idx >> 6), k = (int)(idx & 63);
    size_t b = (size_t)n * 192;
    float r = sigm(gi[b + k] + gh[b + k]);
    float z = sigm(gi[b + 64 + k] + gh[b + 64 + k]);
    float nn = tanhf(gi[b + 128 + k] + r * gh[b + 128 + k]);
    float hv = h[idx];
    h[idx] = (1.0f - z) * nn + z * hv;
}

// ---------------- head output: relu(BN(tmp)) @ W2.T + b2 ----------------
template <int KO>
__global__ void k_head(const float* __restrict__ X, const float* __restrict__ scale,
                       const float* __restrict__ shift, const float* __restrict__ W2,
                       const float* __restrict__ b2, float* __restrict__ out) {
    __shared__ float Wsh[KO * 65];
    __shared__ float sc[64], sf[64];
    int tid = threadIdx.x;
    for (int i = tid; i < KO * 64; i += 256) {
        int k = i >> 6, d = i & 63;
        Wsh[k * 65 + d] = W2[i];
    }
    if (tid < 64) { sc[tid] = scale[tid]; sf[tid] = shift[tid]; }
    __syncthreads();
    int warp = tid >> 5, lane = tid & 31;
    int n = blockIdx.x * 8 + warp;
    if (n >= NNODES) return;
    float acc = (lane < KO) ? b2[lane] : 0.f;
    const float* row = X + (size_t)n * 64;
    for (int d = 0; d < 64; d++) {
        float x = fmaxf(row[d] * sc[d] + sf[d], 0.f);
        if (lane < KO) acc = fmaf(x, Wsh[lane * 65 + d], acc);
    }
    if (lane < KO) out[(size_t)n * KO + lane] = acc;
}

// ---------------- launch ----------------
extern "C" void kernel_launch(void* const* d_in, const int* in_sizes, int n_in,
                              void* d_out, int out_size) {
    const float* v      = (const float*)d_in[0];
    const int*   src    = (const int*)d_in[1];
    const int*   dst    = (const int*)d_in[2];
    const int*   rel    = (const int*)d_in[3];
    const float* norm   = (const float*)d_in[4];
    const float* emb_W  = (const float*)d_in[5];
    const float* emb_b  = (const float*)d_in[6];
    const float* emb_g  = (const float*)d_in[7];
    const float* emb_be = (const float*)d_in[8];
    const float* relW   = (const float*)d_in[9];
    const float* Wih    = (const float*)d_in[10];
    const float* Whh    = (const float*)d_in[11];
    const float* bih    = (const float*)d_in[12];
    const float* bhh    = (const float*)d_in[13];
    const float* ker_g  = (const float*)d_in[14];
    const float* ker_be = (const float*)d_in[15];
    const float* aW1 = (const float*)d_in[16];
    const float* ab1 = (const float*)d_in[17];
    const float* ag  = (const float*)d_in[18];
    const float* abe = (const float*)d_in[19];
    const float* aW2 = (const float*)d_in[20];
    const float* ab2 = (const float*)d_in[21];
    const float* bW1 = (const float*)d_in[22];
    const float* bb1 = (const float*)d_in[23];
    const float* bg  = (const float*)d_in[24];
    const float* bbe = (const float*)d_in[25];
    const float* bW2 = (const float*)d_in[26];
    const float* bb2 = (const float*)d_in[27];
    float* out = (float*)d_out;

    float *p_big1, *p_big2, *p_out, *p_h, *p_swh, *p_tmp, *p_stats, *p_scale, *p_shift;
    int *p_rowptr, *p_cursor, *p_eidx, *p_bsums;
    cudaGetSymbolAddress((void**)&p_big1, g_big1);
    cudaGetSymbolAddress((void**)&p_big2, g_big2);
    cudaGetSymbolAddress((void**)&p_out,  g_out);
    cudaGetSymbolAddress((void**)&p_h,    g_h);
    cudaGetSymbolAddress((void**)&p_swh,  g_swh);
    cudaGetSymbolAddress((void**)&p_tmp,  g_tmp);
    cudaGetSymbolAddress((void**)&p_stats, g_stats);
    cudaGetSymbolAddress((void**)&p_scale, g_scale);
    cudaGetSymbolAddress((void**)&p_shift, g_shift);
    cudaGetSymbolAddress((void**)&p_rowptr, g_rowptr);
    cudaGetSymbolAddress((void**)&p_cursor, g_cursor);
    cudaGetSymbolAddress((void**)&p_eidx,  g_eidx);
    cudaGetSymbolAddress((void**)&p_bsums, g_bsums);

    dim3 mmblk(16, 16);
    int mmgx = (NNODES + 95) / 96;
    const int NSCAN = (NNODES + 1023) / 1024;   // 98

    // ---- CSR build (per launch; deterministic work) ----
    cudaMemsetAsync(p_cursor, 0, NNODES * sizeof(int));
    k_count<<<(NEDGES + 255) / 256, 256>>>(dst, p_cursor);
    k_scanA<<<NSCAN, 1024>>>(p_cursor, p_bsums);
    k_scanB<<<1, 128>>>(p_bsums, NSCAN, p_rowptr);
    k_scanC<<<NSCAN, 1024>>>(p_cursor, p_bsums, p_rowptr, p_cursor);
    k_scatter<<<(NEDGES + 255) / 256, 256>>>(dst, p_cursor, p_eidx);

    // ---- embedding: lin = v @ emb_W.T + b, BN stats fused, then BN+ReLU ----
    cudaMemsetAsync(p_stats, 0, 128 * sizeof(float));
    k_mm64<<<dim3(mmgx, 1), mmblk>>>(v, emb_W, 1, 0, emb_b, 0,
                                     nullptr, nullptr, 0, p_out, 64, p_stats);
    k_finalize<<<1, 64>>>(p_stats, emb_g, emb_be, p_scale, p_shift);
    k_bnrelu<<<25000, 256>>>(p_out, p_scale, p_shift);
    cudaMemsetAsync(p_h, 0, (size_t)NNODES * 64 * sizeof(float));

    // ---- 2 message-passing layers ----
    const float* cur = p_out;
    for (int layer = 0; layer < 2; ++layer) {
        // x3[n, r*64+k] = cur @ rel_weight[r]
        k_mm64<<<dim3(mmgx, 3), mmblk>>>(cur, relW, 0, 4096, nullptr, 0,
                                         nullptr, nullptr, 0, p_big1, 192, nullptr);
        k_aggregate<<<(NNODES * 32 + 255) / 256, 256>>>(p_big1, p_rowptr, p_eidx,
                                                        src, rel, norm, p_swh);
        // gi = swh @ Wih.T + bih ; gh = h @ Whh.T + bhh   (gate blocks via grid.y)
        k_mm64<<<dim3(mmgx, 3), mmblk>>>(p_swh, Wih, 1, 4096, bih, 64,
                                         nullptr, nullptr, 0, p_big1, 192, nullptr);
        k_mm64<<<dim3(mmgx, 3), mmblk>>>(p_h, Whh, 1, 4096, bhh, 64,
                                         nullptr, nullptr, 0, p_big2, 192, nullptr);
        k_gates<<<25000, 256>>>(p_big1, p_big2, p_h);
        cur = p_h;
    }

    // ---- kernel BN on h ----
    cudaMemsetAsync(p_stats, 0, 128 * sizeof(float));
    k_stats64<<<256, dim3(64, 4)>>>(p_h, p_stats);
    k_finalize<<<1, 64>>>(p_stats, ker_g, ker_be, p_scale + 64, p_shift + 64);

    // ---- head A: tmp = BN_ker(h) @ aW1.T + ab1 (stats fused) → BN+ReLU → @ aW2.T ----
    cudaMemsetAsync(p_stats, 0, 128 * sizeof(float));
    k_mm64<<<dim3(mmgx, 1), mmblk>>>(p_h, aW1, 1, 0, ab1, 0,
                                     p_scale + 64, p_shift + 64, 1, p_tmp, 64, p_stats);
    k_finalize<<<1, 64>>>(p_stats, ag, abe, p_scale + 128, p_shift + 128);
    k_head<2><<<12500, 256>>>(p_tmp, p_scale + 128, p_shift + 128, aW2, ab2, out);

    // ---- head B ----
    cudaMemsetAsync(p_stats, 0, 128 * sizeof(float));
    k_mm64<<<dim3(mmgx, 1), mmblk>>>(p_h, bW1, 1, 0, bb1, 0,
                                     p_scale + 64, p_shift + 64, 1, p_tmp, 64, p_stats);
    k_finalize<<<1, 64>>>(p_stats, bg, bbe, p_scale + 192, p_shift + 192);
    k_head<21><<<12500, 256>>>(p_tmp, p_scale + 192, p_shift + 192, bW2, bb2,
                               out + (size_t)NNODES * 2);
}

// round 2
// speedup vs baseline: 1.1663x; 1.1663x over previous
#include <cuda_runtime.h>
#include <math.h>

#define NNODES 100000
#define NEDGES 1600000

// ---------------- scratch (static device globals; no allocations) ----------------
__device__ float g_big1[(size_t)NNODES * 192];   // x3 then gi
__device__ float g_big2[(size_t)NNODES * 192];   // gh
__device__ float g_out [(size_t)NNODES * 64];    // embed lin (raw, pre-BN)
__device__ float g_h   [(size_t)NNODES * 64];    // GRU hidden
__device__ float g_swh [(size_t)NNODES * 64];    // aggregated messages
__device__ float g_tmp [(size_t)NNODES * 64];    // head hidden
__device__ float g_stats[512];                   // 4 slots x (sum[64], sumsq[64])
__device__ float g_scale[4 * 64];
__device__ float g_shift[4 * 64];
__device__ int   g_rowptr[NNODES + 1];
__device__ int   g_cursor[NNODES];
__device__ int   g_ekey [NEDGES];                // (src<<2)|rel, CSR order
__device__ float g_enorm[NEDGES];                // norm, CSR order
__device__ int   g_bsums[128];

// ---------------- f32x2 helpers ----------------
typedef unsigned long long u64t;

__device__ __forceinline__ u64t pk2(float x) {
    u64t r; asm("mov.b64 %0, {%1, %1};" : "=l"(r) : "f"(x)); return r;
}
__device__ __forceinline__ void fma2(u64t& c, u64t a, u64t b) {
    asm("fma.rn.f32x2 %0, %1, %2, %0;" : "+l"(c) : "l"(a), "l"(b));
}
__device__ __forceinline__ void upk2(u64t v, float& lo, float& hi) {
    asm("mov.b64 {%0, %1}, %2;" : "=f"(lo), "=f"(hi) : "l"(v));
}

// ---------------- CSR build ----------------
__global__ void k_count(const int* __restrict__ dst, int* __restrict__ cnt) {
    int e = blockIdx.x * blockDim.x + threadIdx.x;
    if (e < NEDGES) atomicAdd(&cnt[dst[e]], 1);
}

__global__ void k_scanA(const int* __restrict__ cnt, int* __restrict__ bsums) {
    __shared__ int sh[1024];
    int i = blockIdx.x * 1024 + threadIdx.x;
    sh[threadIdx.x] = (i < NNODES) ? cnt[i] : 0;
    __syncthreads();
    for (int off = 512; off > 0; off >>= 1) {
        if (threadIdx.x < off) sh[threadIdx.x] += sh[threadIdx.x + off];
        __syncthreads();
    }
    if (threadIdx.x == 0) bsums[blockIdx.x] = sh[0];
}

__global__ void k_scanB(int* __restrict__ bsums, int nb, int* __restrict__ rowptr) {
    __shared__ int sh[128];
    int t = threadIdx.x;
    int orig = (t < nb) ? bsums[t] : 0;
    sh[t] = orig;
    __syncthreads();
    for (int off = 1; off < 128; off <<= 1) {
        int v = (t >= off) ? sh[t - off] : 0;
        __syncthreads();
        sh[t] += v;
        __syncthreads();
    }
    if (t < nb) bsums[t] = sh[t] - orig;   // exclusive
    if (t == 0) rowptr[NNODES] = NEDGES;
}

__global__ void k_scanC(int* __restrict__ cnt, const int* __restrict__ bsums,
                        int* __restrict__ rowptr, int* __restrict__ cursor) {
    __shared__ int sh[1024];
    int i = blockIdx.x * 1024 + threadIdx.x;
    int orig = (i < NNODES) ? cnt[i] : 0;
    sh[threadIdx.x] = orig;
    __syncthreads();
    for (int off = 1; off < 1024; off <<= 1) {
        int v = (threadIdx.x >= off) ? sh[threadIdx.x - off] : 0;
        __syncthreads();
        sh[threadIdx.x] += v;
        __syncthreads();
    }
    if (i < NNODES) {
        int start = bsums[blockIdx.x] + sh[threadIdx.x] - orig;
        rowptr[i] = start;
        cursor[i] = start;
    }
}

__global__ void k_scatter(const int* __restrict__ dst, const int* __restrict__ src,
                          const int* __restrict__ rel, const float* __restrict__ norm,
                          int* __restrict__ cursor,
                          int* __restrict__ ekey, float* __restrict__ enorm) {
    int e = blockIdx.x * blockDim.x + threadIdx.x;
    if (e < NEDGES) {
        int pos = atomicAdd(&cursor[dst[e]], 1);
        ekey[pos]  = (src[e] << 2) | rel[e];
        enorm[pos] = norm[e];
    }
}

// ---------------- FFMA2 matmul: 128 nodes x 64 cols per block ----------------
// C[n, blockIdx.y*64 + k] = act(A[n,:]) dot W_col(k)  (+ bias)
// W layout: transW ? W[k*64+d] : W[d*64+k] (after +blockIdx.y*w_blk_stride)
// in_act: 0 none, 1 affine, 2 affine+relu
// stats: optional (grid.y==1 only) per-col sum & sumsq of outputs
__global__ __launch_bounds__(128) void k_mm64(
    const float* __restrict__ A,
    const float* __restrict__ W, int transW, int w_blk_stride,
    const float* __restrict__ bias, int bias_blk,
    const float* __restrict__ in_scale, const float* __restrict__ in_shift, int in_act,
    float* __restrict__ C, int c_stride,
    float* __restrict__ stats)
{
    __shared__ float Ws[64 * 64];     // 16 KB
    __shared__ float As[128 * 64];    // 32 KB   (total 48 KB, reused for stats)
    int tx = threadIdx.x;             // 0..7  -> cols [tx*8, tx*8+8)
    int ty = threadIdx.y;             // 0..15 -> nodes ty + 16*j
    int tid = ty * 8 + tx;

    const float* Wb = W + (size_t)blockIdx.y * w_blk_stride;
    for (int i = tid; i < 4096; i += 128) {
        int d = i >> 6, k = i & 63;
        Ws[i] = transW ? Wb[k * 64 + d] : Wb[i];
    }
    int nbase = blockIdx.x * 128;
    for (int i = tid; i < 2048; i += 128) {       // 2048 float4s
        int n = nbase + (i >> 4);
        int c4 = (i & 15);
        float4 v = make_float4(0.f, 0.f, 0.f, 0.f);
        if (n < NNODES) v = reinterpret_cast<const float4*>(A + (size_t)n * 64)[c4];
        if (in_act) {
            int c = c4 * 4;
            v.x = v.x * in_scale[c]     + in_shift[c];
            v.y = v.y * in_scale[c + 1] + in_shift[c + 1];
            v.z = v.z * in_scale[c + 2] + in_shift[c + 2];
            v.w = v.w * in_scale[c + 3] + in_shift[c + 3];
            if (in_act == 2) {
                v.x = fmaxf(v.x, 0.f); v.y = fmaxf(v.y, 0.f);
                v.z = fmaxf(v.z, 0.f); v.w = fmaxf(v.w, 0.f);
            }
        }
        reinterpret_cast<float4*>(As)[i] = v;
    }
    __syncthreads();

    u64t acc[8][4];
#pragma unroll
    for (int j = 0; j < 8; j++)
#pragma unroll
        for (int q = 0; q < 4; q++) acc[j][q] = 0ull;

#pragma unroll 4
    for (int d = 0; d < 64; d++) {
        const u64t* wp = reinterpret_cast<const u64t*>(Ws + d * 64) + tx * 4;
        u64t w0 = wp[0], w1 = wp[1], w2 = wp[2], w3 = wp[3];
        const float* ap = As + ty * 64 + d;
#pragma unroll
        for (int j = 0; j < 8; j++) {
            u64t aa = pk2(ap[j * 16 * 64]);
            fma2(acc[j][0], aa, w0);
            fma2(acc[j][1], aa, w1);
            fma2(acc[j][2], aa, w2);
            fma2(acc[j][3], aa, w3);
        }
    }

    float bv[8];
#pragma unroll
    for (int c = 0; c < 8; c++) bv[c] = 0.f;
    if (bias) {
        const float* bb = bias + blockIdx.y * bias_blk + tx * 8;
#pragma unroll
        for (int c = 0; c < 8; c++) bv[c] = bb[c];
    }

    float s[8], q[8];
#pragma unroll
    for (int c = 0; c < 8; c++) { s[c] = 0.f; q[c] = 0.f; }

#pragma unroll
    for (int j = 0; j < 8; j++) {
        int node = nbase + ty + 16 * j;
        if (node < NNODES) {
            float o[8];
#pragma unroll
            for (int qq = 0; qq < 4; qq++) upk2(acc[j][qq], o[qq * 2], o[qq * 2 + 1]);
#pragma unroll
            for (int c = 0; c < 8; c++) {
                o[c] += bv[c];
                s[c] += o[c];
                q[c] += o[c] * o[c];
            }
            float* cp = C + (size_t)node * c_stride + blockIdx.y * 64 + tx * 8;
            reinterpret_cast<float4*>(cp)[0] = make_float4(o[0], o[1], o[2], o[3]);
            reinterpret_cast<float4*>(cp)[1] = make_float4(o[4], o[5], o[6], o[7]);
        }
    }

    if (stats) {
        __syncthreads();                      // done with Ws; reuse as reduction buf
        float* ssum = Ws;
        float* ssq  = Ws + 64;
        if (tid < 64) { ssum[tid] = 0.f; ssq[tid] = 0.f; }
        __syncthreads();
#pragma unroll
        for (int c = 0; c < 8; c++) {
            atomicAdd(&ssum[tx * 8 + c], s[c]);
            atomicAdd(&ssq [tx * 8 + c], q[c]);
        }
        __syncthreads();
        if (tid < 64) {
            atomicAdd(&stats[tid], ssum[tid]);
            atomicAdd(&stats[64 + tid], ssq[tid]);
        }
    }
}

// ---------------- BN helpers ----------------
__global__ void k_finalize(const float* __restrict__ stats, const float* __restrict__ gamma,
                           const float* __restrict__ beta, float* __restrict__ scale,
                           float* __restrict__ shift) {
    int k = threadIdx.x;
    const float invN = 1.0f / (float)NNODES;
    float mean = stats[k] * invN;
    float var = stats[64 + k] * invN - mean * mean;
    float sc = gamma[k] * rsqrtf(var + 1e-5f);
    scale[k] = sc;
    shift[k] = beta[k] - mean * sc;
}

__global__ void k_stats64(const float* __restrict__ X, float* __restrict__ stats) {
    __shared__ float ssum[64], ssq[64];
    int k = threadIdx.x, ty = threadIdx.y;
    if (ty == 0) { ssum[k] = 0.f; ssq[k] = 0.f; }
    __syncthreads();
    float s = 0.f, q = 0.f;
    for (int n = blockIdx.x * 4 + ty; n < NNODES; n += gridDim.x * 4) {
        float v = X[(size_t)n * 64 + k];
        s += v; q += v * v;
    }
    atomicAdd(&ssum[k], s); atomicAdd(&ssq[k], q);
    __syncthreads();
    if (ty == 0) { atomicAdd(&stats[k], ssum[k]); atomicAdd(&stats[64 + k], ssq[k]); }
}

// ---------------- edge aggregation (gather, warp per node, CSR-ordered data) ----------------
__global__ void k_aggregate(const float* __restrict__ x3, const int* __restrict__ rowptr,
                            const int* __restrict__ ekey, const float* __restrict__ enorm,
                            float* __restrict__ swh) {
    int node = (blockIdx.x * blockDim.x + threadIdx.x) >> 5;
    int lane = threadIdx.x & 31;
    if (node >= NNODES) return;
    int beg = rowptr[node], end = rowptr[node + 1];
    float a0 = 0.f, a1 = 0.f;
    int e = beg;
    for (; e + 1 < end; e += 2) {
        int k0 = ekey[e], k1 = ekey[e + 1];
        float w0 = enorm[e], w1 = enorm[e + 1];
        const float* r0 = x3 + (size_t)(k0 >> 2) * 192 + (k0 & 3) * 64;
        const float* r1 = x3 + (size_t)(k1 >> 2) * 192 + (k1 & 3) * 64;
        float v00 = r0[lane], v01 = r0[lane + 32];
        float v10 = r1[lane], v11 = r1[lane + 32];
        a0 = fmaf(v00, w0, a0); a1 = fmaf(v01, w0, a1);
        a0 = fmaf(v10, w1, a0); a1 = fmaf(v11, w1, a1);
    }
    if (e < end) {
        int k0 = ekey[e];
        float w0 = enorm[e];
        const float* r0 = x3 + (size_t)(k0 >> 2) * 192 + (k0 & 3) * 64;
        a0 = fmaf(r0[lane], w0, a0);
        a1 = fmaf(r0[lane + 32], w0, a1);
    }
    size_t o = (size_t)node * 64;
    swh[o + lane] = a0;
    swh[o + lane + 32] = a1;
}

// ---------------- GRU gate fusion ----------------
__device__ __forceinline__ float sigm(float x) { return 1.0f / (1.0f + expf(-x)); }

// layer 0: h == 0, so gh == bhh exactly
__global__ void k_gates0(const float* __restrict__ gi, const float* __restrict__ bhh,
                         float* __restrict__ h) {
    size_t idx = (size_t)blockIdx.x * blockDim.x + threadIdx.x;
    if (idx >= (size_t)NNODES * 64) return;
    int n = (int)(idx >> 6), k = (int)(idx & 63);
    size_t b = (size_t)n * 192;
    float r = sigm(gi[b + k] + bhh[k]);
    float z = sigm(gi[b + 64 + k] + bhh[64 + k]);
    float nn = tanhf(gi[b + 128 + k] + r * bhh[128 + k]);
    h[idx] = (1.0f - z) * nn;
}

__global__ void k_gates(const float* __restrict__ gi, const float* __restrict__ gh,
                        float* __restrict__ h) {
    size_t idx = (size_t)blockIdx.x * blockDim.x + threadIdx.x;
    if (idx >= (size_t)NNODES * 64) return;
    int n = (int)(idx >> 6), k = (int)(idx & 63);
    size_t b = (size_t)n * 192;
    float r = sigm(gi[b + k] + gh[b + k]);
    float z = sigm(gi[b + 64 + k] + gh[b + 64 + k]);
    float nn = tanhf(gi[b + 128 + k] + r * gh[b + 128 + k]);
    float hv = h[idx];
    h[idx] = (1.0f - z) * nn + z * hv;
}

// ---------------- head output: relu(BN(tmp)) @ W2.T + b2 ----------------
template <int KO>
__global__ void k_head(const float* __restrict__ X, const float* __restrict__ scale,
                       const float* __restrict__ shift, const float* __restrict__ W2,
                       const float* __restrict__ b2, float* __restrict__ out) {
    __shared__ float Wsh[KO * 65];
    __shared__ float sc[64], sf[64];
    int tid = threadIdx.x;
    for (int i = tid; i < KO * 64; i += 256) {
        int k = i >> 6, d = i & 63;
        Wsh[k * 65 + d] = W2[i];
    }
    if (tid < 64) { sc[tid] = scale[tid]; sf[tid] = shift[tid]; }
    __syncthreads();
    int warp = tid >> 5, lane = tid & 31;
    int n = blockIdx.x * 8 + warp;
    if (n >= NNODES) return;
    float acc = (lane < KO) ? b2[lane] : 0.f;
    const float* row = X + (size_t)n * 64;
    for (int d = 0; d < 64; d++) {
        float x = fmaxf(row[d] * sc[d] + sf[d], 0.f);
        if (lane < KO) acc = fmaf(x, Wsh[lane * 65 + d], acc);
    }
    if (lane < KO) out[(size_t)n * KO + lane] = acc;
}

// ---------------- launch ----------------
extern "C" void kernel_launch(void* const* d_in, const int* in_sizes, int n_in,
                              void* d_out, int out_size) {
    const float* v      = (const float*)d_in[0];
    const int*   src    = (const int*)d_in[1];
    const int*   dst    = (const int*)d_in[2];
    const int*   rel    = (const int*)d_in[3];
    const float* norm   = (const float*)d_in[4];
    const float* emb_W  = (const float*)d_in[5];
    const float* emb_b  = (const float*)d_in[6];
    const float* emb_g  = (const float*)d_in[7];
    const float* emb_be = (const float*)d_in[8];
    const float* relW   = (const float*)d_in[9];
    const float* Wih    = (const float*)d_in[10];
    const float* Whh    = (const float*)d_in[11];
    const float* bih    = (const float*)d_in[12];
    const float* bhh    = (const float*)d_in[13];
    const float* ker_g  = (const float*)d_in[14];
    const float* ker_be = (const float*)d_in[15];
    const float* aW1 = (const float*)d_in[16];
    const float* ab1 = (const float*)d_in[17];
    const float* ag  = (const float*)d_in[18];
    const float* abe = (const float*)d_in[19];
    const float* aW2 = (const float*)d_in[20];
    const float* ab2 = (const float*)d_in[21];
    const float* bW1 = (const float*)d_in[22];
    const float* bb1 = (const float*)d_in[23];
    const float* bg  = (const float*)d_in[24];
    const float* bbe = (const float*)d_in[25];
    const float* bW2 = (const float*)d_in[26];
    const float* bb2 = (const float*)d_in[27];
    float* out = (float*)d_out;

    float *p_big1, *p_big2, *p_out, *p_h, *p_swh, *p_tmp, *p_stats, *p_scale, *p_shift;
    int *p_rowptr, *p_cursor, *p_ekey, *p_bsums;
    float *p_enorm;
    cudaGetSymbolAddress((void**)&p_big1, g_big1);
    cudaGetSymbolAddress((void**)&p_big2, g_big2);
    cudaGetSymbolAddress((void**)&p_out,  g_out);
    cudaGetSymbolAddress((void**)&p_h,    g_h);
    cudaGetSymbolAddress((void**)&p_swh,  g_swh);
    cudaGetSymbolAddress((void**)&p_tmp,  g_tmp);
    cudaGetSymbolAddress((void**)&p_stats, g_stats);
    cudaGetSymbolAddress((void**)&p_scale, g_scale);
    cudaGetSymbolAddress((void**)&p_shift, g_shift);
    cudaGetSymbolAddress((void**)&p_rowptr, g_rowptr);
    cudaGetSymbolAddress((void**)&p_cursor, g_cursor);
    cudaGetSymbolAddress((void**)&p_ekey,  g_ekey);
    cudaGetSymbolAddress((void**)&p_enorm, g_enorm);
    cudaGetSymbolAddress((void**)&p_bsums, g_bsums);

    dim3 mmblk(8, 16);
    int mmgx = (NNODES + 127) / 128;               // 782
    const int NSCAN = (NNODES + 1023) / 1024;      // 98

    // ---- CSR build + stats clear ----
    cudaMemsetAsync(p_cursor, 0, NNODES * sizeof(int));
    cudaMemsetAsync(p_stats, 0, 512 * sizeof(float));
    k_count<<<(NEDGES + 255) / 256, 256>>>(dst, p_cursor);
    k_scanA<<<NSCAN, 1024>>>(p_cursor, p_bsums);
    k_scanB<<<1, 128>>>(p_bsums, NSCAN, p_rowptr);
    k_scanC<<<NSCAN, 1024>>>(p_cursor, p_bsums, p_rowptr, p_cursor);
    k_scatter<<<(NEDGES + 255) / 256, 256>>>(dst, src, rel, norm, p_cursor,
                                             p_ekey, p_enorm);

    // ---- embedding linear (stats fused); BN+ReLU folded into layer-0 x3 mm ----
    k_mm64<<<dim3(mmgx, 1), mmblk>>>(v, emb_W, 1, 0, emb_b, 0,
                                     nullptr, nullptr, 0, p_out, 64, p_stats);
    k_finalize<<<1, 64>>>(p_stats, emb_g, emb_be, p_scale, p_shift);

    // ---- layer 0 (h == 0: skip gh matmul entirely) ----
    k_mm64<<<dim3(mmgx, 3), mmblk>>>(p_out, relW, 0, 4096, nullptr, 0,
                                     p_scale, p_shift, 2, p_big1, 192, nullptr);
    k_aggregate<<<(NNODES * 32 + 255) / 256, 256>>>(p_big1, p_rowptr, p_ekey,
                                                    p_enorm, p_swh);
    k_mm64<<<dim3(mmgx, 3), mmblk>>>(p_swh, Wih, 1, 4096, bih, 64,
                                     nullptr, nullptr, 0, p_big1, 192, nullptr);
    k_gates0<<<25000, 256>>>(p_big1, bhh, p_h);

    // ---- layer 1 ----
    k_mm64<<<dim3(mmgx, 3), mmblk>>>(p_h, relW, 0, 4096, nullptr, 0,
                                     nullptr, nullptr, 0, p_big1, 192, nullptr);
    k_aggregate<<<(NNODES * 32 + 255) / 256, 256>>>(p_big1, p_rowptr, p_ekey,
                                                    p_enorm, p_swh);
    k_mm64<<<dim3(mmgx, 3), mmblk>>>(p_swh, Wih, 1, 4096, bih, 64,
                                     nullptr, nullptr, 0, p_big1, 192, nullptr);
    k_mm64<<<dim3(mmgx, 3), mmblk>>>(p_h, Whh, 1, 4096, bhh, 64,
                                     nullptr, nullptr, 0, p_big2, 192, nullptr);
    k_gates<<<25000, 256>>>(p_big1, p_big2, p_h);

    // ---- kernel BN on h ----
    k_stats64<<<256, dim3(64, 4)>>>(p_h, p_stats + 128);
    k_finalize<<<1, 64>>>(p_stats + 128, ker_g, ker_be, p_scale + 64, p_shift + 64);

    // ---- head A ----
    k_mm64<<<dim3(mmgx, 1), mmblk>>>(p_h, aW1, 1, 0, ab1, 0,
                                     p_scale + 64, p_shift + 64, 1, p_tmp, 64,
                                     p_stats + 256);
    k_finalize<<<1, 64>>>(p_stats + 256, ag, abe, p_scale + 128, p_shift + 128);
    k_head<2><<<12500, 256>>>(p_tmp, p_scale + 128, p_shift + 128, aW2, ab2, out);

    // ---- head B ----
    k_mm64<<<dim3(mmgx, 1), mmblk>>>(p_h, bW1, 1, 0, bb1, 0,
                                     p_scale + 64, p_shift + 64, 1, p_tmp, 64,
                                     p_stats + 384);
    k_finalize<<<1, 64>>>(p_stats + 384, bg, bbe, p_scale + 192, p_shift + 192);
    k_head<21><<<12500, 256>>>(p_tmp, p_scale + 192, p_shift + 192, bW2, bb2,
                               out + (size_t)NNODES * 2);
}